// round 4
// baseline (speedup 1.0000x reference)
#include <cuda_runtime.h>

#define OSC 2048
#define MH  4096
#define NTHR 256

#define XM_P  4104
#define XK_P  4100
#define XF_P  2052
#define XH_P  4100

// ---------------- scratch (no allocs allowed) ----------------
__device__ __align__(16) float g_xm [4 * XM_P];
__device__ __align__(16) float g_xk1[4 * XK_P], g_xk2[4 * XK_P];
__device__ __align__(16) float g_xf1[4 * XF_P], g_xf2[4 * XF_P];
__device__ __align__(16) float g_xh1[4 * XH_P], g_xh2[4 * XH_P];
__device__ __align__(16) float g_mnew[MH];
__device__ __align__(16) float g_h1new[OSC], g_h2new[OSC];
__device__ __align__(16) float g_k1new[OSC], g_k2new[OSC];
__device__ __align__(16) float g_f1new[OSC], g_f2new[OSC];
// partial sums + ticket counters for split h-cell reduction
__device__ __align__(16) float g_hp[OSC][12];
__device__ unsigned g_hcnt[OSC];

__device__ __forceinline__ float sigm(float v) { return 1.0f / (1.0f + __expf(-v)); }
__device__ __forceinline__ int cls_off(int h) { return (4 - h) & 3; }

__device__ __forceinline__ float4 ldw(const float* p) {
    return __ldcs(reinterpret_cast<const float4*>(p));
}
__device__ __forceinline__ float4 ldx(const float* p) {
    return *reinterpret_cast<const float4*>(p);
}
__device__ __forceinline__ float dot4(float4 a, float4 b) {
    return a.x * b.x + a.y * b.y + a.z * b.z + a.w * b.w;
}

template <int NS>
__device__ __forceinline__ void blockReduce(float (&acc)[NS], float (&out)[NS]) {
    __shared__ float sm[NS][NTHR / 32];
    const int lane = threadIdx.x & 31;
    const int wid  = threadIdx.x >> 5;
#pragma unroll
    for (int s = 0; s < NS; s++) {
        float v = acc[s];
        v += __shfl_down_sync(0xffffffffu, v, 16);
        v += __shfl_down_sync(0xffffffffu, v, 8);
        v += __shfl_down_sync(0xffffffffu, v, 4);
        v += __shfl_down_sync(0xffffffffu, v, 2);
        v += __shfl_down_sync(0xffffffffu, v, 1);
        if (lane == 0) sm[s][wid] = v;
    }
    __syncthreads();
    if (threadIdx.x == 0) {
#pragma unroll
        for (int s = 0; s < NS; s++) {
            float v = 0.0f;
#pragma unroll
            for (int w = 0; w < NTHR / 32; w++) v += sm[s][w];
            out[s] = v;
        }
    }
}

// -------- single-stream GRU unit (for the m cell) --------
__device__ __forceinline__ void gru_unit_single(
    const float* __restrict__ wih, const float* __restrict__ whh,
    const float* __restrict__ bih, const float* __restrict__ bhh,
    const float* __restrict__ xbufs, int pad, int D,
    const float* __restrict__ hprev, int H, int j,
    float* __restrict__ newout)
{
    float acc[6] = {0, 0, 0, 0, 0, 0};
    const int head = (4 - (j & 3)) & 3;
    const float* xc = xbufs + head * pad + cls_off(head);
    const float* wr = wih + (size_t)j * D;
    const float* wz = wih + (size_t)(H + j) * D;
    const float* wn = wih + (size_t)(2 * H + j) * D;
    const int nvec = (D - head) >> 2;
    const int tail = D - head - (nvec << 2);

    if (threadIdx.x < (unsigned)head) {
        int d = threadIdx.x;
        float xv = xc[d];
        acc[0] += wr[d] * xv; acc[1] += wz[d] * xv; acc[2] += wn[d] * xv;
    }
    int c = threadIdx.x;
    for (; c + NTHR < nvec; c += 2 * NTHR) {
        int d0 = head + (c << 2);
        int d1 = d0 + (NTHR << 2);
        float4 a0 = ldw(wr + d0), b0 = ldw(wz + d0), e0 = ldw(wn + d0);
        float4 a1 = ldw(wr + d1), b1 = ldw(wz + d1), e1 = ldw(wn + d1);
        float4 x0 = ldx(xc + d0), x1 = ldx(xc + d1);
        acc[0] += dot4(a0, x0); acc[1] += dot4(b0, x0); acc[2] += dot4(e0, x0);
        acc[0] += dot4(a1, x1); acc[1] += dot4(b1, x1); acc[2] += dot4(e1, x1);
    }
    if (c < nvec) {
        int d0 = head + (c << 2);
        float4 a0 = ldw(wr + d0), b0 = ldw(wz + d0), e0 = ldw(wn + d0);
        float4 x0 = ldx(xc + d0);
        acc[0] += dot4(a0, x0); acc[1] += dot4(b0, x0); acc[2] += dot4(e0, x0);
    }
    if (threadIdx.x < (unsigned)tail) {
        int d = head + (nvec << 2) + threadIdx.x;
        float xv = xc[d];
        acc[0] += wr[d] * xv; acc[1] += wz[d] * xv; acc[2] += wn[d] * xv;
    }

    const float* ur = whh + (size_t)j * H;
    const float* uz = whh + (size_t)(H + j) * H;
    const float* un = whh + (size_t)(2 * H + j) * H;
    const int nvh = H >> 2;
    c = threadIdx.x;
    for (; c + NTHR < nvh; c += 2 * NTHR) {
        int d0 = c << 2, d1 = d0 + (NTHR << 2);
        float4 a0 = ldw(ur + d0), b0 = ldw(uz + d0), e0 = ldw(un + d0);
        float4 a1 = ldw(ur + d1), b1 = ldw(uz + d1), e1 = ldw(un + d1);
        float4 h0 = ldx(hprev + d0), h1v = ldx(hprev + d1);
        acc[3] += dot4(a0, h0); acc[4] += dot4(b0, h0); acc[5] += dot4(e0, h0);
        acc[3] += dot4(a1, h1v); acc[4] += dot4(b1, h1v); acc[5] += dot4(e1, h1v);
    }
    if (c < nvh) {
        int d0 = c << 2;
        float4 a0 = ldw(ur + d0), b0 = ldw(uz + d0), e0 = ldw(un + d0);
        float4 h0 = ldx(hprev + d0);
        acc[3] += dot4(a0, h0); acc[4] += dot4(b0, h0); acc[5] += dot4(e0, h0);
    }

    float s[6];
    blockReduce<6>(acc, s);
    if (threadIdx.x == 0) {
        float r = sigm(s[0] + bih[j] + s[3] + bhh[j]);
        float z = sigm(s[1] + bih[H + j] + s[4] + bhh[H + j]);
        float n = tanhf(s[2] + bih[2 * H + j] + r * (s[5] + bhh[2 * H + j]));
        newout[j] = (1.0f - z) * n + z * hprev[j];
    }
}

// -------- dual-stream GRU unit (k/f cells) --------
__device__ __forceinline__ void gru_unit_dual(
    const float* __restrict__ wih, const float* __restrict__ whh,
    const float* __restrict__ bih, const float* __restrict__ bhh,
    const float* __restrict__ x1bufs, const float* __restrict__ x2bufs, int pad, int D,
    const float* __restrict__ h1, const float* __restrict__ h2, int H, int j,
    float* __restrict__ out1, float* __restrict__ out2)
{
    float acc[12] = {0, 0, 0, 0, 0, 0, 0, 0, 0, 0, 0, 0};
    const int head = (4 - (j & 3)) & 3;
    const int off  = head * pad + cls_off(head);
    const float* x1c = x1bufs + off;
    const float* x2c = x2bufs + off;
    const float* wr = wih + (size_t)j * D;
    const float* wz = wih + (size_t)(H + j) * D;
    const float* wn = wih + (size_t)(2 * H + j) * D;
    const int nvec = (D - head) >> 2;
    const int tail = D - head - (nvec << 2);

    if (threadIdx.x < (unsigned)head) {
        int d = threadIdx.x;
        float a = x1c[d], b = x2c[d];
        float w0 = wr[d], w1 = wz[d], w2 = wn[d];
        acc[0] += w0 * a; acc[1] += w1 * a; acc[2] += w2 * a;
        acc[3] += w0 * b; acc[4] += w1 * b; acc[5] += w2 * b;
    }
    int c = threadIdx.x;
    for (; c + NTHR < nvec; c += 2 * NTHR) {
        int d0 = head + (c << 2), d1 = d0 + (NTHR << 2);
        float4 a0 = ldw(wr + d0), b0 = ldw(wz + d0), e0 = ldw(wn + d0);
        float4 a1 = ldw(wr + d1), b1 = ldw(wz + d1), e1 = ldw(wn + d1);
        float4 p0 = ldx(x1c + d0), q0 = ldx(x2c + d0);
        float4 p1 = ldx(x1c + d1), q1 = ldx(x2c + d1);
        acc[0] += dot4(a0, p0); acc[1] += dot4(b0, p0); acc[2] += dot4(e0, p0);
        acc[3] += dot4(a0, q0); acc[4] += dot4(b0, q0); acc[5] += dot4(e0, q0);
        acc[0] += dot4(a1, p1); acc[1] += dot4(b1, p1); acc[2] += dot4(e1, p1);
        acc[3] += dot4(a1, q1); acc[4] += dot4(b1, q1); acc[5] += dot4(e1, q1);
    }
    if (c < nvec) {
        int d0 = head + (c << 2);
        float4 a0 = ldw(wr + d0), b0 = ldw(wz + d0), e0 = ldw(wn + d0);
        float4 p0 = ldx(x1c + d0), q0 = ldx(x2c + d0);
        acc[0] += dot4(a0, p0); acc[1] += dot4(b0, p0); acc[2] += dot4(e0, p0);
        acc[3] += dot4(a0, q0); acc[4] += dot4(b0, q0); acc[5] += dot4(e0, q0);
    }
    if (threadIdx.x < (unsigned)tail) {
        int d = head + (nvec << 2) + threadIdx.x;
        float a = x1c[d], b = x2c[d];
        float w0 = wr[d], w1 = wz[d], w2 = wn[d];
        acc[0] += w0 * a; acc[1] += w1 * a; acc[2] += w2 * a;
        acc[3] += w0 * b; acc[4] += w1 * b; acc[5] += w2 * b;
    }

    const float* ur = whh + (size_t)j * H;
    const float* uz = whh + (size_t)(H + j) * H;
    const float* un = whh + (size_t)(2 * H + j) * H;
    const int nvh = H >> 2;
    c = threadIdx.x;
    for (; c + NTHR < nvh; c += 2 * NTHR) {
        int d0 = c << 2, d1 = d0 + (NTHR << 2);
        float4 a0 = ldw(ur + d0), b0 = ldw(uz + d0), e0 = ldw(un + d0);
        float4 a1 = ldw(ur + d1), b1 = ldw(uz + d1), e1 = ldw(un + d1);
        float4 p0 = ldx(h1 + d0), q0 = ldx(h2 + d0);
        float4 p1 = ldx(h1 + d1), q1 = ldx(h2 + d1);
        acc[6] += dot4(a0, p0); acc[7]  += dot4(b0, p0); acc[8]  += dot4(e0, p0);
        acc[9] += dot4(a0, q0); acc[10] += dot4(b0, q0); acc[11] += dot4(e0, q0);
        acc[6] += dot4(a1, p1); acc[7]  += dot4(b1, p1); acc[8]  += dot4(e1, p1);
        acc[9] += dot4(a1, q1); acc[10] += dot4(b1, q1); acc[11] += dot4(e1, q1);
    }
    if (c < nvh) {
        int d0 = c << 2;
        float4 a0 = ldw(ur + d0), b0 = ldw(uz + d0), e0 = ldw(un + d0);
        float4 p0 = ldx(h1 + d0), q0 = ldx(h2 + d0);
        acc[6] += dot4(a0, p0); acc[7]  += dot4(b0, p0); acc[8]  += dot4(e0, p0);
        acc[9] += dot4(a0, q0); acc[10] += dot4(b0, q0); acc[11] += dot4(e0, q0);
    }

    float s[12];
    blockReduce<12>(acc, s);
    if (threadIdx.x == 0) {
        float br = bih[j], bz = bih[H + j], bn = bih[2 * H + j];
        float cr = bhh[j], cz = bhh[H + j], cn = bhh[2 * H + j];
        {
            float r = sigm(s[0] + br + s[6] + cr);
            float z = sigm(s[1] + bz + s[7] + cz);
            float n = tanhf(s[2] + bn + r * (s[8] + cn));
            out1[j] = (1.0f - z) * n + z * h1[j];
        }
        {
            float r = sigm(s[3] + br + s[9] + cr);
            float z = sigm(s[4] + bz + s[10] + cz);
            float n = tanhf(s[5] + bn + r * (s[11] + cn));
            out2[j] = (1.0f - z) * n + z * h2[j];
        }
    }
}

// ---------------- K0: build shifted copies + zero h-partials ----------------
__global__ __launch_bounds__(NTHR) void k_prep(
    const float* __restrict__ x,
    const float* __restrict__ h1s, const float* __restrict__ h2s,
    const float* __restrict__ k1s, const float* __restrict__ k2s,
    const float* __restrict__ f1s, const float* __restrict__ f2s)
{
    int i = blockIdx.x * blockDim.x + threadIdx.x;
    if (i == 0) {
#pragma unroll
        for (int h = 0; h < 4; h++) {
            int o = cls_off(h);
            g_xm [h * XM_P + o + 0] = x[0];
            g_xm [h * XM_P + o + 1] = x[1];
            g_xm [h * XM_P + o + 2] = x[8];
            g_xm [h * XM_P + o + 3] = x[9];
            g_xm [h * XM_P + o + 4] = x[10];
            g_xk1[h * XK_P + o] = x[3]; g_xk2[h * XK_P + o] = x[6];
            g_xf1[h * XF_P + o] = x[4]; g_xf2[h * XF_P + o] = x[7];
            g_xh1[h * XH_P + o] = x[2]; g_xh2[h * XH_P + o] = x[5];
        }
    }
    if (i < OSC) {
        float h1v = h1s[i], h2v = h2s[i], f1v = f1s[i], f2v = f2s[i];
        float k1v = k1s[i], k2v = k2s[i];
#pragma unroll
        for (int h = 0; h < 4; h++) {
            int o = cls_off(h);
            g_xm [h * XM_P + o + 5 + i]        = h1v;
            g_xm [h * XM_P + o + 5 + OSC + i]  = h2v;
            g_xk1[h * XK_P + o + 1 + i]        = h1v;
            g_xk1[h * XK_P + o + 1 + OSC + i]  = f1v;
            g_xk2[h * XK_P + o + 1 + i]        = h2v;
            g_xk2[h * XK_P + o + 1 + OSC + i]  = f2v;
            g_xf1[h * XF_P + o + 1 + i]        = f1v;
            g_xf2[h * XF_P + o + 1 + i]        = f2v;
            g_xh1[h * XH_P + o + 1 + OSC + i]  = k1v;
            g_xh2[h * XH_P + o + 1 + OSC + i]  = k2v;
        }
#pragma unroll
        for (int s = 0; s < 12; s++) g_hp[i][s] = 0.0f;
        g_hcnt[i] = 0u;
    }
}

// ---------------- K1: m (single) + k (dual) + f (dual) GRUs ----------------
__global__ __launch_bounds__(NTHR) void k_gru_mkf(
    const float* __restrict__ m_wih, const float* __restrict__ m_whh,
    const float* __restrict__ m_bih, const float* __restrict__ m_bhh,
    const float* __restrict__ m_s,
    const float* __restrict__ k_wih, const float* __restrict__ k_whh,
    const float* __restrict__ k_bih, const float* __restrict__ k_bhh,
    const float* __restrict__ k1s, const float* __restrict__ k2s,
    const float* __restrict__ f_wih, const float* __restrict__ f_whh,
    const float* __restrict__ f_bih, const float* __restrict__ f_bhh,
    const float* __restrict__ f1s, const float* __restrict__ f2s)
{
    int b = blockIdx.x;
    if (b < MH) {
        gru_unit_single(m_wih, m_whh, m_bih, m_bhh, g_xm, XM_P, 5 + 2 * OSC,
                        m_s, MH, b, g_mnew);
    } else if (b < MH + OSC) {
        gru_unit_dual(k_wih, k_whh, k_bih, k_bhh, g_xk1, g_xk2, XK_P, 1 + 2 * OSC,
                      k1s, k2s, OSC, b - MH, g_k1new, g_k2new);
    } else {
        gru_unit_dual(f_wih, f_whh, f_bih, f_bhh, g_xf1, g_xf2, XF_P, 1 + OSC,
                      f1s, f2s, OSC, b - MH - OSC, g_f1new, g_f2new);
    }
}

// ---------------- K2: out_m row r (fully batched 8-load body) ----------------
__global__ __launch_bounds__(NTHR) void k_mout(
    const float* __restrict__ w, const float* __restrict__ bias)
{
    int r = blockIdx.x;
    const float* wr = w + (size_t)r * MH;
    // MH/4 = 1024 = 4 * NTHR -> fully unrolled straight-line body
    int d0 = threadIdx.x << 2;
    float4 a0 = ldw(wr + d0),        a1 = ldw(wr + d0 + 1024);
    float4 a2 = ldw(wr + d0 + 2048), a3 = ldw(wr + d0 + 3072);
    float4 m0 = ldx(g_mnew + d0),        m1 = ldx(g_mnew + d0 + 1024);
    float4 m2 = ldx(g_mnew + d0 + 2048), m3 = ldx(g_mnew + d0 + 3072);
    float acc[1];
    acc[0] = dot4(a0, m0) + dot4(a1, m1) + dot4(a2, m2) + dot4(a3, m3);
    float s[1];
    blockReduce<1>(acc, s);
    if (threadIdx.x == 0) {
        float v = s[0] + bias[r];
        if (r < OSC) {
#pragma unroll
            for (int h = 0; h < 4; h++) g_xh1[h * XH_P + cls_off(h) + 1 + r] = v;
        } else {
            int rr = r - OSC;
#pragma unroll
            for (int h = 0; h < 4; h++) g_xh2[h * XH_P + cls_off(h) + 1 + rr] = v;
        }
    }
}

// ---------------- K3: h cells, 3-way column-split per unit ----------------
// chunk 0: wih vector cols [0,512)   (+ head scalars)
// chunk 1: wih vector cols [512,nvec) (+ tail scalars)
// chunk 2: whh (512 vector cols)
// Each block atomically accumulates 6 partials; 3rd finisher applies gates.
__global__ __launch_bounds__(NTHR) void k_gru_h3(
    const float* __restrict__ wih, const float* __restrict__ whh,
    const float* __restrict__ bih, const float* __restrict__ bhh,
    const float* __restrict__ h1s, const float* __restrict__ h2s)
{
    const int j = blockIdx.x & (OSC - 1);
    const int chunk = blockIdx.x >> 11;
    const int D = 1 + 2 * OSC;   // 4097
    const int H = OSC;
    const int tid = threadIdx.x;
    const int head = (4 - (j & 3)) & 3;

    float acc[6] = {0, 0, 0, 0, 0, 0};
    int base;

    if (chunk < 2) {
        const int off = head * XH_P + cls_off(head);
        const float* x1c = g_xh1 + off;
        const float* x2c = g_xh2 + off;
        const float* wr = wih + (size_t)j * D;
        const float* wz = wih + (size_t)(H + j) * D;
        const float* wn = wih + (size_t)(2 * H + j) * D;
        const int nvec = (D - head) >> 2;
        base = 0;
        if (chunk == 0) {
            if (tid < head) {
                float a = x1c[tid], b = x2c[tid];
                float w0 = wr[tid], w1 = wz[tid], w2 = wn[tid];
                acc[0] += w0 * a; acc[1] += w1 * a; acc[2] += w2 * a;
                acc[3] += w0 * b; acc[4] += w1 * b; acc[5] += w2 * b;
            }
            int d0 = head + (tid << 2);
            int d1 = d0 + (NTHR << 2);
            float4 a0 = ldw(wr + d0), b0 = ldw(wz + d0), e0 = ldw(wn + d0);
            float4 a1 = ldw(wr + d1), b1 = ldw(wz + d1), e1 = ldw(wn + d1);
            float4 p0 = ldx(x1c + d0), q0 = ldx(x2c + d0);
            float4 p1 = ldx(x1c + d1), q1 = ldx(x2c + d1);
            acc[0] += dot4(a0, p0) + dot4(a1, p1);
            acc[1] += dot4(b0, p0) + dot4(b1, p1);
            acc[2] += dot4(e0, p0) + dot4(e1, p1);
            acc[3] += dot4(a0, q0) + dot4(a1, q1);
            acc[4] += dot4(b0, q0) + dot4(b1, q1);
            acc[5] += dot4(e0, q0) + dot4(e1, q1);
        } else {
            const int tail = D - head - (nvec << 2);
            int c0 = 512 + tid;            // always < nvec (nvec >= 1023)
            int c1 = 768 + tid;            // guard against nvec = 1023
            int d0 = head + (c0 << 2);
            int d1 = head + (c1 << 2);
            bool ok1 = (c1 < nvec);
            float4 a0 = ldw(wr + d0), b0 = ldw(wz + d0), e0 = ldw(wn + d0);
            float4 p0 = ldx(x1c + d0), q0 = ldx(x2c + d0);
            if (ok1) {
                float4 a1 = ldw(wr + d1), b1 = ldw(wz + d1), e1 = ldw(wn + d1);
                float4 p1 = ldx(x1c + d1), q1 = ldx(x2c + d1);
                acc[0] += dot4(a1, p1); acc[1] += dot4(b1, p1); acc[2] += dot4(e1, p1);
                acc[3] += dot4(a1, q1); acc[4] += dot4(b1, q1); acc[5] += dot4(e1, q1);
            }
            acc[0] += dot4(a0, p0); acc[1] += dot4(b0, p0); acc[2] += dot4(e0, p0);
            acc[3] += dot4(a0, q0); acc[4] += dot4(b0, q0); acc[5] += dot4(e0, q0);
            if (tid < tail) {
                int d = head + (nvec << 2) + tid;
                float a = x1c[d], b = x2c[d];
                float w0 = wr[d], w1 = wz[d], w2 = wn[d];
                acc[0] += w0 * a; acc[1] += w1 * a; acc[2] += w2 * a;
                acc[3] += w0 * b; acc[4] += w1 * b; acc[5] += w2 * b;
            }
        }
    } else {
        const float* ur = whh + (size_t)j * H;
        const float* uz = whh + (size_t)(H + j) * H;
        const float* un = whh + (size_t)(2 * H + j) * H;
        base = 6;
        int d0 = tid << 2;
        int d1 = d0 + (NTHR << 2);
        float4 a0 = ldw(ur + d0), b0 = ldw(uz + d0), e0 = ldw(un + d0);
        float4 a1 = ldw(ur + d1), b1 = ldw(uz + d1), e1 = ldw(un + d1);
        float4 p0 = ldx(h1s + d0), q0 = ldx(h2s + d0);
        float4 p1 = ldx(h1s + d1), q1 = ldx(h2s + d1);
        acc[0] += dot4(a0, p0) + dot4(a1, p1);
        acc[1] += dot4(b0, p0) + dot4(b1, p1);
        acc[2] += dot4(e0, p0) + dot4(e1, p1);
        acc[3] += dot4(a0, q0) + dot4(a1, q1);
        acc[4] += dot4(b0, q0) + dot4(b1, q1);
        acc[5] += dot4(e0, q0) + dot4(e1, q1);
    }

    float s[6];
    blockReduce<6>(acc, s);
    if (tid == 0) {
#pragma unroll
        for (int i = 0; i < 6; i++) atomicAdd(&g_hp[j][base + i], s[i]);
        __threadfence();
        unsigned ticket = atomicAdd(&g_hcnt[j], 1u);
        if (ticket == 2u) {
            float p[12];
#pragma unroll
            for (int i = 0; i < 12; i++) p[i] = __ldcg(&g_hp[j][i]);
            float br = bih[j], bz = bih[OSC + j], bn = bih[2 * OSC + j];
            float cr = bhh[j], cz = bhh[OSC + j], cn = bhh[2 * OSC + j];
            {
                float r = sigm(p[0] + br + p[6] + cr);
                float z = sigm(p[1] + bz + p[7] + cz);
                float n = tanhf(p[2] + bn + r * (p[8] + cn));
                g_h1new[j] = (1.0f - z) * n + z * h1s[j];
            }
            {
                float r = sigm(p[3] + br + p[9] + cr);
                float z = sigm(p[4] + bz + p[10] + cz);
                float n = tanhf(p[5] + bn + r * (p[11] + cn));
                g_h2new[j] = (1.0f - z) * n + z * h2s[j];
            }
        }
    }
}

// ---------------- K4: six output dot products ----------------
__global__ __launch_bounds__(NTHR) void k_heads(
    const float* __restrict__ h_ow, const float* __restrict__ h_ob,
    const float* __restrict__ k_ow, const float* __restrict__ k_ob,
    const float* __restrict__ f_ow, const float* __restrict__ f_ob,
    float* __restrict__ out)
{
    int b = blockIdx.x;
    const float* vec;
    const float* w;
    const float* bp;
    switch (b) {
        case 0: vec = g_h1new; w = h_ow; bp = h_ob; break;
        case 1: vec = g_k1new; w = k_ow; bp = k_ob; break;
        case 2: vec = g_f1new; w = f_ow; bp = f_ob; break;
        case 3: vec = g_h2new; w = h_ow; bp = h_ob; break;
        case 4: vec = g_k2new; w = k_ow; bp = k_ob; break;
        default: vec = g_f2new; w = f_ow; bp = f_ob; break;
    }
    int d0 = threadIdx.x << 2;
    float4 a0 = ldx(w + d0), a1 = ldx(w + d0 + 1024);
    float4 v0 = ldx(vec + d0), v1 = ldx(vec + d0 + 1024);
    float acc[1];
    acc[0] = dot4(a0, v0) + dot4(a1, v1);
    float s[1];
    blockReduce<1>(acc, s);
    if (threadIdx.x == 0) out[b] = s[0] + bp[0];
}

// ---------------- launch ----------------
extern "C" void kernel_launch(void* const* d_in, const int* in_sizes, int n_in,
                              void* d_out, int out_size)
{
    const float* x      = (const float*)d_in[0];
    const float* m_s    = (const float*)d_in[1];
    const float* h1_s   = (const float*)d_in[2];
    const float* h2_s   = (const float*)d_in[3];
    const float* k1_s   = (const float*)d_in[4];
    const float* k2_s   = (const float*)d_in[5];
    const float* f1_s   = (const float*)d_in[6];
    const float* f2_s   = (const float*)d_in[7];
    const float* m_wih  = (const float*)d_in[8];
    const float* m_whh  = (const float*)d_in[9];
    const float* m_bih  = (const float*)d_in[10];
    const float* m_bhh  = (const float*)d_in[11];
    const float* m_ow   = (const float*)d_in[12];
    const float* m_ob   = (const float*)d_in[13];
    const float* h_wih  = (const float*)d_in[14];
    const float* h_whh  = (const float*)d_in[15];
    const float* h_bih  = (const float*)d_in[16];
    const float* h_bhh  = (const float*)d_in[17];
    const float* h_ow   = (const float*)d_in[18];
    const float* h_ob   = (const float*)d_in[19];
    const float* k_wih  = (const float*)d_in[20];
    const float* k_whh  = (const float*)d_in[21];
    const float* k_bih  = (const float*)d_in[22];
    const float* k_bhh  = (const float*)d_in[23];
    const float* k_ow   = (const float*)d_in[24];
    const float* k_ob   = (const float*)d_in[25];
    const float* f_wih  = (const float*)d_in[26];
    const float* f_whh  = (const float*)d_in[27];
    const float* f_bih  = (const float*)d_in[28];
    const float* f_bhh  = (const float*)d_in[29];
    const float* f_ow   = (const float*)d_in[30];
    const float* f_ob   = (const float*)d_in[31];
    float* out = (float*)d_out;

    k_prep<<<(OSC + NTHR - 1) / NTHR, NTHR>>>(x, h1_s, h2_s, k1_s, k2_s, f1_s, f2_s);
    k_gru_mkf<<<MH + 2 * OSC, NTHR>>>(m_wih, m_whh, m_bih, m_bhh, m_s,
                                      k_wih, k_whh, k_bih, k_bhh, k1_s, k2_s,
                                      f_wih, f_whh, f_bih, f_bhh, f1_s, f2_s);
    k_mout<<<MH, NTHR>>>(m_ow, m_ob);
    k_gru_h3<<<3 * OSC, NTHR>>>(h_wih, h_whh, h_bih, h_bhh, h1_s, h2_s);
    k_heads<<<6, NTHR>>>(h_ow, h_ob, k_ow, k_ob, f_ow, f_ob, out);
}